// round 7
// baseline (speedup 1.0000x reference)
#include <cuda_runtime.h>
#include <math.h>
#include <stdint.h>

// Problem constants
#define Bsz 4
#define Tn  2048
#define Cn  1024
#define Hn  8
#define Dn  128
#define DffN 4096
#define Mrows (Bsz*Tn)   // 8192
#define SCALE 11.313708498984761f  // sqrt(128), multiply (faithful to reference)

// ---------------- scratch ----------------
__device__ float g_h [(size_t)Mrows*Cn];
__device__ float g_q [(size_t)Mrows*Cn];
__device__ float g_k [(size_t)Mrows*Cn];
__device__ float g_v [(size_t)Mrows*Cn];
__device__ float g_x1[(size_t)Mrows*Cn];
__device__ float g_h2[(size_t)Mrows*Cn];
__device__ float g_ff[(size_t)Mrows*DffN];

// ---------------- helpers ----------------
__device__ __forceinline__ uint32_t cvt_tf32(float x){
    uint32_t u; asm("cvt.rna.tf32.f32 %0, %1;" : "=r"(u) : "f"(x)); return u;
}
__device__ __forceinline__ void mma8(float* d, const uint32_t* a, const uint32_t* b){
    asm volatile("mma.sync.aligned.m16n8k8.row.col.f32.tf32.tf32.f32 "
        "{%0,%1,%2,%3},{%4,%5,%6,%7},{%8,%9},{%0,%1,%2,%3};"
        : "+f"(d[0]),"+f"(d[1]),"+f"(d[2]),"+f"(d[3])
        : "r"(a[0]),"r"(a[1]),"r"(a[2]),"r"(a[3]),"r"(b[0]),"r"(b[1]));
}

// ---------------- LayerNorm ----------------
__global__ __launch_bounds__(256) void ln_kernel(
    const float* __restrict__ x, const float* __restrict__ g,
    const float* __restrict__ bta, float* __restrict__ out)
{
    long row = blockIdx.x;
    int tid = threadIdx.x;
    const float4* xr = (const float4*)(x + row*(long)Cn);
    float4 v = xr[tid];
    float s = v.x + v.y + v.z + v.w;

    __shared__ float sh[34];
    int lane = tid & 31, wid = tid >> 5;
    #pragma unroll
    for (int o = 16; o > 0; o >>= 1) s += __shfl_xor_sync(0xffffffffu, s, o);
    if (lane == 0) sh[wid] = s;
    __syncthreads();
    if (tid == 0) {
        float t = 0.f;
        #pragma unroll
        for (int w = 0; w < 8; w++) t += sh[w];
        sh[32] = t * (1.0f / Cn);
    }
    __syncthreads();
    float mu = sh[32];
    float dx0 = v.x - mu, dx1 = v.y - mu, dx2 = v.z - mu, dx3 = v.w - mu;
    float ss = dx0*dx0 + dx1*dx1 + dx2*dx2 + dx3*dx3;
    #pragma unroll
    for (int o = 16; o > 0; o >>= 1) ss += __shfl_xor_sync(0xffffffffu, ss, o);
    __syncthreads();
    if (lane == 0) sh[wid] = ss;
    __syncthreads();
    if (tid == 0) {
        float t = 0.f;
        #pragma unroll
        for (int w = 0; w < 8; w++) t += sh[w];
        sh[33] = rsqrtf(t * (1.0f / Cn) + 1e-5f);
    }
    __syncthreads();
    float rstd = sh[33];
    float4 gg = ((const float4*)g)[tid];
    float4 bb = ((const float4*)bta)[tid];
    float4 o4;
    o4.x = dx0 * rstd * gg.x + bb.x;
    o4.y = dx1 * rstd * gg.y + bb.y;
    o4.z = dx2 * rstd * gg.z + bb.z;
    o4.w = dx3 * rstd * gg.w + bb.w;
    ((float4*)(out + row*(long)Cn))[tid] = o4;
}

// ---------------- TF32 MMA GEMM: 128x128 block, BK=16, 256 thr ----------------
// Fragment-major smem: A frags -> LDS.128, B frags -> LDS.64.
// A layout (per 16-k tile): idx = (k>>3)*1024 + (r>>4)*128 + lsw*4 + w
//   l = ((r&7)<<2)|(k&3), lsw = l^(r&7), w = ((k>>2)&1)*2 + ((r>>3)&1)
// B layout: idx = (k>>3)*1056 + (n>>3)*66 + l*2 + w ; l = ((n&7)<<2)|(k&3), w=(k>>2)&1
// Ping-pong double buffered. SPLIT=3 -> 3xTF32.
template<int SPLIT>
__global__ __launch_bounds__(256) void mma_gemm(
    const float* __restrict__ A, const float* __restrict__ Bm, float* __restrict__ Cm,
    int M, int N, int K, int lda, int ldb, int ldc,
    long sB, long sC,
    const float* __restrict__ bias, int applyRelu,
    const float* __restrict__ res, int ldres)
{
    constexpr int AW = 2048;                 // A tile words
    constexpr int BW = 2112;                 // B tile words (2*1056)
    constexpr int oAl = AW;                  // split3 only
    constexpr int oBh = (SPLIT==3) ? 2*AW : AW;
    constexpr int oBl = oBh + BW;
    constexpr int NTW = (SPLIT==3) ? (2*AW + 2*BW) : (AW + BW);
    extern __shared__ uint32_t smem[];       // 2 * NTW words

    int bz = blockIdx.z;
    Bm += bz * sB;
    Cm += bz * sC;

    int brow = blockIdx.y*128, bcol = blockIdx.x*128;
    int tid = threadIdx.x, lane = tid&31, wid = tid>>5;
    int wm = wid>>2, wn = wid&3;
    int lsw = lane ^ (lane>>2);

    float acc[4][4][4];
    #pragma unroll
    for (int i=0;i<4;i++)
        #pragma unroll
        for (int j=0;j<4;j++)
            #pragma unroll
            for (int t=0;t<4;t++) acc[i][j][t]=0.f;

    int a_r0 = tid>>2;
    int a_k0 = (tid&3)*4;
    const float* Ap = A + (long)(brow + a_r0)*lda + a_k0;
    int b_k0 = tid>>5;
    int b_c0 = lane*4;
    const float* Bp = Bm + (long)b_k0*ldb + bcol + b_c0;

    float4 av0, av1, bv0, bv1;

    auto gload = [&](){
        av0 = *(const float4*)(Ap);
        av1 = *(const float4*)(Ap + (long)64*lda);
        bv0 = *(const float4*)(Bp);
        bv1 = *(const float4*)(Bp + (long)8*ldb);
        Ap += 16; Bp += (long)16*ldb;
    };

    // precomputed store indices (loop-invariant parts)
    int st_rr  = a_r0 & 15;            // same for row and row+64
    int st_r4a = a_r0 >> 4;
    int st_r4b = (a_r0 + 64) >> 4;
    int st_wk  = (tid & 1) * 2;        // ((k>>2)&1)*2 for k = (tid&3)*4+j
    int st_rb  = (st_rr >> 3) & 1;
    int st_bk3 = b_k0 & 3;
    int st_bw  = (b_k0 >> 2) & 1;

    auto store_tile = [&](uint32_t* base){
        uint32_t* Ah = base;
        uint32_t* Al = base + oAl;
        uint32_t* Bh = base + oBh;
        uint32_t* Bl = base + oBl;
        float va[4] = {av0.x,av0.y,av0.z,av0.w};
        float vb[4] = {av1.x,av1.y,av1.z,av1.w};
        #pragma unroll
        for (int j=0;j<4;j++){
            int k  = a_k0 + j;
            int l  = ((st_rr&7)<<2) | j;
            int ls = l ^ (st_rr&7);
            int w  = st_wk + st_rb;
            int idA = (k>>3)*1024 + ls*4 + w;
            uint32_t h0 = cvt_tf32(va[j]);
            Ah[idA + st_r4a*128] = h0;
            uint32_t h1 = cvt_tf32(vb[j]);
            Ah[idA + st_r4b*128] = h1;
            if (SPLIT==3){
                Al[idA + st_r4a*128] = cvt_tf32(va[j]-__uint_as_float(h0));
                Al[idA + st_r4b*128] = cvt_tf32(vb[j]-__uint_as_float(h1));
            }
        }
        float wa[4] = {bv0.x,bv0.y,bv0.z,bv0.w};
        float wb[4] = {bv1.x,bv1.y,bv1.z,bv1.w};
        #pragma unroll
        for (int j=0;j<4;j++){
            int n = b_c0 + j;
            int l = ((n&7)<<2) | st_bk3;
            int idB = (n>>3)*66 + l*2 + st_bw;
            uint32_t h0 = cvt_tf32(wa[j]);
            Bh[idB] = h0;
            uint32_t h1 = cvt_tf32(wb[j]);
            Bh[idB + 1056] = h1;
            if (SPLIT==3){
                Bl[idB]        = cvt_tf32(wa[j]-__uint_as_float(h0));
                Bl[idB + 1056] = cvt_tf32(wb[j]-__uint_as_float(h1));
            }
        }
    };

    auto compute_tile = [&](const uint32_t* base){
        const uint32_t* Ah = base;
        const uint32_t* Al = base + oAl;
        const uint32_t* Bh = base + oBh;
        const uint32_t* Bl = base + oBl;
        #pragma unroll
        for (int kg = 0; kg < 2; kg++){
            uint32_t bhf[4][2], blf[4][2];
            #pragma unroll
            for (int nt=0;nt<4;nt++){
                uint2 t = *(const uint2*)(Bh + kg*1056 + (wn*4+nt)*66 + lane*2);
                bhf[nt][0]=t.x; bhf[nt][1]=t.y;
                if (SPLIT==3){
                    uint2 u = *(const uint2*)(Bl + kg*1056 + (wn*4+nt)*66 + lane*2);
                    blf[nt][0]=u.x; blf[nt][1]=u.y;
                }
            }
            #pragma unroll
            for (int mt=0;mt<4;mt++){
                uint4 a4 = *(const uint4*)(Ah + kg*1024 + (wm*4+mt)*128 + lsw*4);
                uint32_t ah[4] = {a4.x,a4.y,a4.z,a4.w};
                uint32_t alr[4];
                if (SPLIT==3){
                    uint4 l4 = *(const uint4*)(Al + kg*1024 + (wm*4+mt)*128 + lsw*4);
                    alr[0]=l4.x; alr[1]=l4.y; alr[2]=l4.z; alr[3]=l4.w;
                }
                #pragma unroll
                for (int nt=0;nt<4;nt++){
                    mma8(acc[mt][nt], ah, bhf[nt]);
                    if (SPLIT==3){
                        mma8(acc[mt][nt], ah, blf[nt]);
                        mma8(acc[mt][nt], alr, bhf[nt]);
                    }
                }
            }
        }
    };

    // prologue
    gload();
    store_tile(smem);
    __syncthreads();

    int nIter = K >> 4;
    for (int i = 0; i < nIter; i++) {
        uint32_t* cur = smem + (size_t)(i & 1) * NTW;
        uint32_t* nxt = smem + (size_t)((i & 1) ^ 1) * NTW;
        bool hasNext = (i + 1 < nIter);
        if (hasNext) gload();
        compute_tile(cur);
        if (hasNext) store_tile(nxt);
        __syncthreads();
    }

    // epilogue
    #pragma unroll
    for (int mt=0;mt<4;mt++){
        int r0 = brow + wm*64 + mt*16 + (lane>>2);
        #pragma unroll
        for (int nt=0;nt<4;nt++){
            int c = bcol + wn*32 + nt*8 + (lane&3)*2;
            float2 v0 = make_float2(acc[mt][nt][0], acc[mt][nt][1]);
            float2 v1 = make_float2(acc[mt][nt][2], acc[mt][nt][3]);
            if (bias){
                float b0=bias[c], b1=bias[c+1];
                v0.x+=b0; v0.y+=b1; v1.x+=b0; v1.y+=b1;
            }
            if (applyRelu){
                v0.x=fmaxf(v0.x,0.f); v0.y=fmaxf(v0.y,0.f);
                v1.x=fmaxf(v1.x,0.f); v1.y=fmaxf(v1.y,0.f);
            }
            if (res){
                v0.x += res[(long)r0*ldres + c];     v0.y += res[(long)r0*ldres + c+1];
                v1.x += res[(long)(r0+8)*ldres + c]; v1.y += res[(long)(r0+8)*ldres + c+1];
            }
            *(float2*)(Cm + (long)r0*ldc + c)     = v0;
            *(float2*)(Cm + (long)(r0+8)*ldc + c) = v1;
        }
    }
}

// ---------------- Flash attention with TF32 MMA (fragment-major smem) ----------------
// Q: a-frag layout, per kg stride 520 (16 kg over d=128), 4 m-tiles
// K: b-frag layout, per kg stride 536 (16 kg), 8 n-tiles of 66
// V: b-frag layout, per kg stride 1056 (8 kg over s=64), 16 n-tiles of 66
#define QWRD 8320   // 16*520
#define KWRD 8576   // 16*536
#define VWRD 8448   // 8*1056
#define SSd  68
#define ATTN_WORDS (2*QWRD + 2*KWRD + VWRD + 64*SSd + 3*64 + 8*64)
#define ATTN_BYTES (ATTN_WORDS*4)

__global__ __launch_bounds__(256) void attn_mma(
    const float* __restrict__ Q, const float* __restrict__ K, const float* __restrict__ V,
    const float* __restrict__ x, float* __restrict__ x1)
{
    extern __shared__ uint32_t sm[];
    uint32_t* Qh = sm;
    uint32_t* Ql = Qh + QWRD;
    uint32_t* Kh = Ql + QWRD;
    uint32_t* Kl = Kh + KWRD;
    uint32_t* Vt = Kl + KWRD;
    float* Ssm  = (float*)(Vt + VWRD);
    float* mrow = Ssm + 64*SSd;
    float* lrow = mrow + 64;
    float* arow = lrow + 64;
    float* pmax = arow + 64;
    float* psum = pmax + 4*64;

    int bh = blockIdx.y; int b = bh>>3, h = bh&7;
    int q0 = blockIdx.x*64;
    int tid = threadIdx.x, lane = tid&31, wid = tid>>5;
    int wm = wid>>1, wn = wid&1;   // 4(m) x 2(n)
    int lsw = lane ^ (lane>>2);

    const float* Qg = Q + ((long)b*Tn + q0)*Cn + h*Dn;
    const float* Kg = K + (long)b*Tn*Cn + h*Dn;
    const float* Vg = V + (long)b*Tn*Cn + h*Dn;

    // Load + split Q tile into fragment-major layout (once)
    #pragma unroll
    for (int it=0; it<8; it++){
        int idx = tid + it*256;
        int r = idx>>5, c4 = (idx&31)*4;
        float4 t = *(const float4*)(Qg + (long)r*Cn + c4);
        float v[4] = {t.x,t.y,t.z,t.w};
        int rr = r & 15;
        int rb = (rr>>3)&1;
        int r4 = r>>4;
        #pragma unroll
        for (int j=0;j<4;j++){
            int k = c4 + j;
            int l  = ((rr&7)<<2) | j;
            int ls = l ^ (rr&7);
            int w  = ((k>>2)&1)*2 + rb;
            int id = (k>>3)*520 + r4*128 + ls*4 + w;
            uint32_t hh = cvt_tf32(v[j]);
            Qh[id] = hh;
            Ql[id] = cvt_tf32(v[j]-__uint_as_float(hh));
        }
    }
    if (tid < 64){ mrow[tid] = -1e30f; lrow[tid] = 0.f; }

    float accO[8][4];
    #pragma unroll
    for (int i=0;i<8;i++)
        #pragma unroll
        for (int j=0;j<4;j++) accO[i][j]=0.f;

    // register staging for K/V tiles
    float4 kreg[8], vreg[8];
    #pragma unroll
    for (int it=0; it<8; it++){
        int idx = tid + it*256;
        int r = idx>>5, c4 = (idx&31)*4;
        kreg[it] = *(const float4*)(Kg + (long)r*Cn + c4);
        vreg[it] = *(const float4*)(Vg + (long)r*Cn + c4);
    }

    for (int kt = 0; kt < Tn/64; kt++) {
        __syncthreads();   // prev PV / softmax reads done
        // commit staged K/V -> fragment-major smem
        #pragma unroll
        for (int it=0; it<8; it++){
            int idx = tid + it*256;
            int r = idx>>5, c4 = (idx&31)*4;
            float kv[4] = {kreg[it].x, kreg[it].y, kreg[it].z, kreg[it].w};
            float vv[4] = {vreg[it].x, vreg[it].y, vreg[it].z, vreg[it].w};
            int kl_base = ((r&7)<<2);
            int kn_base = (r>>3)*66;
            int vl_or   = r&3;
            int vw      = (r>>2)&1;
            int vkg     = (r>>3)*1056;
            #pragma unroll
            for (int j=0;j<4;j++){
                int k = c4 + j;
                // K (b-frag over n=r, k=d)
                int idK = (k>>3)*536 + kn_base + (kl_base|j)*2 + ((k>>2)&1);
                uint32_t hh = cvt_tf32(kv[j]);
                Kh[idK] = hh;
                Kl[idK] = cvt_tf32(kv[j]-__uint_as_float(hh));
                // V (b-frag over n=col, k=s-row r)
                int c = c4 + j;
                int idV = vkg + (c>>3)*66 + ((((c&7)<<2)|vl_or))*2 + vw;
                Vt[idV] = cvt_tf32(vv[j]);
            }
        }
        __syncthreads();

        // prefetch next K/V tile into registers
        if (kt + 1 < Tn/64) {
            const float* Kgt = Kg + (long)(kt+1)*64*Cn;
            const float* Vgt = Vg + (long)(kt+1)*64*Cn;
            #pragma unroll
            for (int it=0; it<8; it++){
                int idx = tid + it*256;
                int r = idx>>5, c4 = (idx&31)*4;
                kreg[it] = *(const float4*)(Kgt + (long)r*Cn + c4);
                vreg[it] = *(const float4*)(Vgt + (long)r*Cn + c4);
            }
        }

        // S = Q K^T (3xTF32), warp tile 16x32
        float accS[4][4];
        #pragma unroll
        for (int i=0;i<4;i++)
            #pragma unroll
            for (int j=0;j<4;j++) accS[i][j]=0.f;

        {
            const uint32_t* qb  = Qh + wm*128 + lsw*4;
            const uint32_t* qlb = Ql + wm*128 + lsw*4;
            const uint32_t* kb  = Kh + (wn*4)*66 + lane*2;
            const uint32_t* klb = Kl + (wn*4)*66 + lane*2;
            #pragma unroll
            for (int kg=0; kg<16; kg++){
                uint4 a4 = *(const uint4*)(qb  + kg*520);
                uint4 l4 = *(const uint4*)(qlb + kg*520);
                uint32_t ah[4] = {a4.x,a4.y,a4.z,a4.w};
                uint32_t al[4] = {l4.x,l4.y,l4.z,l4.w};
                #pragma unroll
                for (int nt=0;nt<4;nt++){
                    uint2 b2 = *(const uint2*)(kb  + kg*536 + nt*66);
                    uint2 c2 = *(const uint2*)(klb + kg*536 + nt*66);
                    uint32_t bhf[2] = {b2.x, b2.y};
                    uint32_t blf[2] = {c2.x, c2.y};
                    mma8(accS[nt], ah, bhf);
                    mma8(accS[nt], ah, blf);
                    mma8(accS[nt], al, bhf);
                }
            }
        }
        {
            int r = wm*16 + (lane>>2);
            #pragma unroll
            for (int nt=0;nt<4;nt++){
                int c = wn*32 + nt*8 + (lane&3)*2;
                Ssm[r*SSd + c]       = accS[nt][0]*SCALE;
                Ssm[r*SSd + c + 1]   = accS[nt][1]*SCALE;
                Ssm[(r+8)*SSd + c]   = accS[nt][2]*SCALE;
                Ssm[(r+8)*SSd + c+1] = accS[nt][3]*SCALE;
            }
        }
        __syncthreads();

        // softmax: 4 threads per row
        {
            int r = tid & 63, qd = tid >> 6;
            float* Sr = Ssm + r*SSd + qd*16;
            float mt_ = -1e30f;
            #pragma unroll
            for (int j=0;j<16;j++) mt_ = fmaxf(mt_, Sr[j]);
            pmax[qd*64 + r] = mt_;
            __syncthreads();
            float mold = mrow[r];
            float mnew = fmaxf(mold,
                         fmaxf(fmaxf(pmax[r], pmax[64+r]), fmaxf(pmax[128+r], pmax[192+r])));
            float s_ = 0.f;
            #pragma unroll
            for (int j=0;j<16;j++){
                float p = __expf(Sr[j] - mnew);
                Sr[j] = p; s_ += p;
            }
            psum[qd*64 + r] = s_;
            __syncthreads();
            if (qd == 0){
                float al_ = __expf(mold - mnew);
                lrow[r] = lrow[r]*al_ + psum[r] + psum[64+r] + psum[128+r] + psum[192+r];
                mrow[r] = mnew;
                arow[r] = al_;
            }
        }
        __syncthreads();

        // rescale + PV (1xTF32), warp tile 16x64
        {
            float a0 = arow[wm*16 + (lane>>2)];
            float a1 = arow[wm*16 + (lane>>2) + 8];
            #pragma unroll
            for (int nt=0;nt<8;nt++){
                accO[nt][0]*=a0; accO[nt][1]*=a0;
                accO[nt][2]*=a1; accO[nt][3]*=a1;
            }
            const uint32_t* vb = Vt + (wn*8)*66 + lane*2;
            int r = wm*16 + (lane>>2);
            #pragma unroll
            for (int kg=0; kg<8; kg++){
                int kk = kg*8 + (lane&3);
                uint32_t ap[4];
                ap[0]=cvt_tf32(Ssm[r*SSd + kk]);
                ap[1]=cvt_tf32(Ssm[(r+8)*SSd + kk]);
                ap[2]=cvt_tf32(Ssm[r*SSd + kk + 4]);
                ap[3]=cvt_tf32(Ssm[(r+8)*SSd + kk + 4]);
                #pragma unroll
                for (int nt=0;nt<8;nt++){
                    uint2 b2 = *(const uint2*)(vb + kg*1056 + nt*66);
                    uint32_t bp[2] = {b2.x, b2.y};
                    mma8(accO[nt], ap, bp);
                }
            }
        }
    }

    __syncthreads();
    // epilogue: x1 = x + O/l
    {
        int r = wm*16 + (lane>>2);
        float i0 = 1.f/lrow[r], i1 = 1.f/lrow[r+8];
        long row0 = (long)b*Tn + q0 + r;
        #pragma unroll
        for (int nt=0;nt<8;nt++){
            int c = h*Dn + wn*64 + nt*8 + (lane&3)*2;
            long o0 = row0*Cn + c, o1 = (row0+8)*Cn + c;
            float2 v0 = make_float2(accO[nt][0]*i0 + x[o0], accO[nt][1]*i0 + x[o0+1]);
            float2 v1 = make_float2(accO[nt][2]*i1 + x[o1], accO[nt][3]*i1 + x[o1+1]);
            *(float2*)(x1 + o0) = v0;
            *(float2*)(x1 + o1) = v1;
        }
    }
}

// ---------------- host launcher ----------------
extern "C" void kernel_launch(void* const* d_in, const int* in_sizes, int n_in,
                              void* d_out, int out_size)
{
    const float* x    = (const float*)d_in[0];
    const float* wq   = (const float*)d_in[1];
    const float* wk   = (const float*)d_in[2];
    const float* wv   = (const float*)d_in[3];
    const float* w1   = (const float*)d_in[4];
    const float* b1   = (const float*)d_in[5];
    const float* w2   = (const float*)d_in[6];
    const float* b2   = (const float*)d_in[7];
    const float* ln1g = (const float*)d_in[8];
    const float* ln1b = (const float*)d_in[9];
    const float* ln2g = (const float*)d_in[10];
    const float* ln2b = (const float*)d_in[11];
    float* out = (float*)d_out;

    float *h, *q, *k, *v, *x1, *h2, *ff;
    cudaGetSymbolAddress((void**)&h,  g_h);
    cudaGetSymbolAddress((void**)&q,  g_q);
    cudaGetSymbolAddress((void**)&k,  g_k);
    cudaGetSymbolAddress((void**)&v,  g_v);
    cudaGetSymbolAddress((void**)&x1, g_x1);
    cudaGetSymbolAddress((void**)&h2, g_h2);
    cudaGetSymbolAddress((void**)&ff, g_ff);

    // dynamic smem: split1 = 2*(2048+2112)*4 = 33280 B ; split3 = 2*(4096+4224)*4 = 66560 B
    const int SM1 = 2*(2048+2112)*4;
    const int SM3 = 2*(2*2048+2*2112)*4;

    cudaFuncSetAttribute(attn_mma, cudaFuncAttributeMaxDynamicSharedMemorySize,
                         ATTN_BYTES);
    cudaFuncSetAttribute(mma_gemm<1>, cudaFuncAttributeMaxDynamicSharedMemorySize, SM1);
    cudaFuncSetAttribute(mma_gemm<3>, cudaFuncAttributeMaxDynamicSharedMemorySize, SM3);

    // 1) LN1
    ln_kernel<<<Mrows, 256>>>(x, ln1g, ln1b, h);

    // 2) projections: q,k in 3xTF32 (score chain), v in 1xTF32
    dim3 pg(1, Mrows/128, Hn);
    mma_gemm<3><<<pg, 256, SM3>>>(h, wq, q, Mrows, Dn, Cn, Cn, Dn, Cn,
                             (long)Cn*Dn, (long)Dn, nullptr, 0, nullptr, 0);
    mma_gemm<3><<<pg, 256, SM3>>>(h, wk, k, Mrows, Dn, Cn, Cn, Dn, Cn,
                             (long)Cn*Dn, (long)Dn, nullptr, 0, nullptr, 0);
    mma_gemm<1><<<pg, 256, SM1>>>(h, wv, v, Mrows, Dn, Cn, Cn, Dn, Cn,
                             (long)Cn*Dn, (long)Dn, nullptr, 0, nullptr, 0);

    // 3) attention + residual
    attn_mma<<<dim3(Tn/64, Bsz*Hn), 256, ATTN_BYTES>>>(q, k, v, x, x1);

    // 4) LN2
    ln_kernel<<<Mrows, 256>>>(x1, ln2g, ln2b, h2);

    // 5) FF1: relu(h2 @ w1 + b1)
    mma_gemm<1><<<dim3(DffN/128, Mrows/128, 1), 256, SM1>>>(h2, w1, ff, Mrows, DffN, Cn,
                             Cn, DffN, DffN, 0L, 0L, b1, 1, nullptr, 0);

    // 6) FF2: out = x1 + (ff @ w2 + b2)
    mma_gemm<1><<<dim3(Cn/128, Mrows/128, 1), 256, SM1>>>(ff, w2, out, Mrows, Cn, DffN,
                             DffN, Cn, Cn, 0L, 0L, b2, 0, x1, Cn);
}

// round 8
// speedup vs baseline: 1.2126x; 1.2126x over previous
#include <cuda_runtime.h>
#include <math.h>
#include <stdint.h>

// Problem constants
#define Bsz 4
#define Tn  2048
#define Cn  1024
#define Hn  8
#define Dn  128
#define DffN 4096
#define Mrows (Bsz*Tn)   // 8192
#define SCALE 11.313708498984761f  // sqrt(128), multiply (faithful to reference)

// ---------------- scratch ----------------
__device__ float g_h [(size_t)Mrows*Cn];
__device__ float g_q [(size_t)Mrows*Cn];
__device__ float g_k [(size_t)Mrows*Cn];
__device__ float g_v [(size_t)Mrows*Cn];
__device__ float g_x1[(size_t)Mrows*Cn];
__device__ float g_h2[(size_t)Mrows*Cn];
__device__ float g_ff[(size_t)Mrows*DffN];

// ---------------- helpers ----------------
__device__ __forceinline__ uint32_t cvt_tf32(float x){
    uint32_t u; asm("cvt.rna.tf32.f32 %0, %1;" : "=r"(u) : "f"(x)); return u;
}
__device__ __forceinline__ void mma8(float* d, const uint32_t* a, const uint32_t* b){
    asm volatile("mma.sync.aligned.m16n8k8.row.col.f32.tf32.tf32.f32 "
        "{%0,%1,%2,%3},{%4,%5,%6,%7},{%8,%9},{%0,%1,%2,%3};"
        : "+f"(d[0]),"+f"(d[1]),"+f"(d[2]),"+f"(d[3])
        : "r"(a[0]),"r"(a[1]),"r"(a[2]),"r"(a[3]),"r"(b[0]),"r"(b[1]));
}

// ---------------- LayerNorm ----------------
__global__ __launch_bounds__(256) void ln_kernel(
    const float* __restrict__ x, const float* __restrict__ g,
    const float* __restrict__ bta, float* __restrict__ out)
{
    long row = blockIdx.x;
    int tid = threadIdx.x;
    const float4* xr = (const float4*)(x + row*(long)Cn);
    float4 v = xr[tid];
    float s = v.x + v.y + v.z + v.w;

    __shared__ float sh[34];
    int lane = tid & 31, wid = tid >> 5;
    #pragma unroll
    for (int o = 16; o > 0; o >>= 1) s += __shfl_xor_sync(0xffffffffu, s, o);
    if (lane == 0) sh[wid] = s;
    __syncthreads();
    if (tid == 0) {
        float t = 0.f;
        #pragma unroll
        for (int w = 0; w < 8; w++) t += sh[w];
        sh[32] = t * (1.0f / Cn);
    }
    __syncthreads();
    float mu = sh[32];
    float dx0 = v.x - mu, dx1 = v.y - mu, dx2 = v.z - mu, dx3 = v.w - mu;
    float ss = dx0*dx0 + dx1*dx1 + dx2*dx2 + dx3*dx3;
    #pragma unroll
    for (int o = 16; o > 0; o >>= 1) ss += __shfl_xor_sync(0xffffffffu, ss, o);
    __syncthreads();
    if (lane == 0) sh[wid] = ss;
    __syncthreads();
    if (tid == 0) {
        float t = 0.f;
        #pragma unroll
        for (int w = 0; w < 8; w++) t += sh[w];
        sh[33] = rsqrtf(t * (1.0f / Cn) + 1e-5f);
    }
    __syncthreads();
    float rstd = sh[33];
    float4 gg = ((const float4*)g)[tid];
    float4 bb = ((const float4*)bta)[tid];
    float4 o4;
    o4.x = dx0 * rstd * gg.x + bb.x;
    o4.y = dx1 * rstd * gg.y + bb.y;
    o4.z = dx2 * rstd * gg.z + bb.z;
    o4.w = dx3 * rstd * gg.w + bb.w;
    ((float4*)(out + row*(long)Cn))[tid] = o4;
}

// ---------------- TF32 MMA GEMM: 128x128 block, BK=16, 256 thr ----------------
// Fragment-major smem (A frags -> LDS.128, B frags -> LDS.64), ping-pong
// double buffered, __launch_bounds__(256,2) pins 128 regs -> 2 CTAs/SM.
template<int SPLIT>
__global__ __launch_bounds__(256, 2) void mma_gemm(
    const float* __restrict__ A, const float* __restrict__ Bm, float* __restrict__ Cm,
    int M, int N, int K, int lda, int ldb, int ldc,
    long sB, long sC,
    const float* __restrict__ bias, int applyRelu,
    const float* __restrict__ res, int ldres)
{
    constexpr int AW = 2048;                 // A tile words
    constexpr int BW = 2112;                 // B tile words (2*1056)
    constexpr int oAl = AW;                  // split3 only
    constexpr int oBh = (SPLIT==3) ? 2*AW : AW;
    constexpr int oBl = oBh + BW;
    constexpr int NTW = (SPLIT==3) ? (2*AW + 2*BW) : (AW + BW);
    extern __shared__ uint32_t smem[];       // 2 * NTW words

    int bz = blockIdx.z;
    Bm += bz * sB;
    Cm += bz * sC;

    int brow = blockIdx.y*128, bcol = blockIdx.x*128;
    int tid = threadIdx.x, lane = tid&31, wid = tid>>5;
    int wm = wid>>2, wn = wid&3;
    int lsw = lane ^ (lane>>2);

    float acc[4][4][4];
    #pragma unroll
    for (int i=0;i<4;i++)
        #pragma unroll
        for (int j=0;j<4;j++)
            #pragma unroll
            for (int t=0;t<4;t++) acc[i][j][t]=0.f;

    int a_r0 = tid>>2;
    int a_k0 = (tid&3)*4;
    const float* Ap = A + (long)(brow + a_r0)*lda + a_k0;
    int b_k0 = tid>>5;
    int b_c0 = lane*4;
    const float* Bp = Bm + (long)b_k0*ldb + bcol + b_c0;

    float4 av0, av1, bv0, bv1;

    auto gload = [&](){
        av0 = *(const float4*)(Ap);
        av1 = *(const float4*)(Ap + (long)64*lda);
        bv0 = *(const float4*)(Bp);
        bv1 = *(const float4*)(Bp + (long)8*ldb);
        Ap += 16; Bp += (long)16*ldb;
    };

    // precomputed store indices (loop-invariant parts)
    int st_rr  = a_r0 & 15;
    int st_r4a = a_r0 >> 4;
    int st_r4b = (a_r0 + 64) >> 4;
    int st_wk  = (tid & 1) * 2;
    int st_rb  = (st_rr >> 3) & 1;
    int st_bk3 = b_k0 & 3;
    int st_bw  = (b_k0 >> 2) & 1;

    auto store_tile = [&](uint32_t* base){
        uint32_t* Ah = base;
        uint32_t* Al = base + oAl;
        uint32_t* Bh = base + oBh;
        uint32_t* Bl = base + oBl;
        float va[4] = {av0.x,av0.y,av0.z,av0.w};
        float vb[4] = {av1.x,av1.y,av1.z,av1.w};
        #pragma unroll
        for (int j=0;j<4;j++){
            int k  = a_k0 + j;
            int l  = ((st_rr&7)<<2) | j;
            int ls = l ^ (st_rr&7);
            int w  = st_wk + st_rb;
            int idA = (k>>3)*1024 + ls*4 + w;
            uint32_t h0 = cvt_tf32(va[j]);
            Ah[idA + st_r4a*128] = h0;
            uint32_t h1 = cvt_tf32(vb[j]);
            Ah[idA + st_r4b*128] = h1;
            if (SPLIT==3){
                Al[idA + st_r4a*128] = cvt_tf32(va[j]-__uint_as_float(h0));
                Al[idA + st_r4b*128] = cvt_tf32(vb[j]-__uint_as_float(h1));
            }
        }
        float wa[4] = {bv0.x,bv0.y,bv0.z,bv0.w};
        float wb[4] = {bv1.x,bv1.y,bv1.z,bv1.w};
        #pragma unroll
        for (int j=0;j<4;j++){
            int n = b_c0 + j;
            int l = ((n&7)<<2) | st_bk3;
            int idB = (n>>3)*66 + l*2 + st_bw;
            uint32_t h0 = cvt_tf32(wa[j]);
            Bh[idB] = h0;
            uint32_t h1 = cvt_tf32(wb[j]);
            Bh[idB + 1056] = h1;
            if (SPLIT==3){
                Bl[idB]        = cvt_tf32(wa[j]-__uint_as_float(h0));
                Bl[idB + 1056] = cvt_tf32(wb[j]-__uint_as_float(h1));
            }
        }
    };

    auto compute_tile = [&](const uint32_t* base){
        const uint32_t* Ah = base;
        const uint32_t* Al = base + oAl;
        const uint32_t* Bh = base + oBh;
        const uint32_t* Bl = base + oBl;
        #pragma unroll
        for (int kg = 0; kg < 2; kg++){
            uint32_t bhf[4][2], blf[4][2];
            #pragma unroll
            for (int nt=0;nt<4;nt++){
                uint2 t = *(const uint2*)(Bh + kg*1056 + (wn*4+nt)*66 + lane*2);
                bhf[nt][0]=t.x; bhf[nt][1]=t.y;
                if (SPLIT==3){
                    uint2 u = *(const uint2*)(Bl + kg*1056 + (wn*4+nt)*66 + lane*2);
                    blf[nt][0]=u.x; blf[nt][1]=u.y;
                }
            }
            #pragma unroll
            for (int mt=0;mt<4;mt++){
                uint4 a4 = *(const uint4*)(Ah + kg*1024 + (wm*4+mt)*128 + lsw*4);
                uint32_t ah[4] = {a4.x,a4.y,a4.z,a4.w};
                uint32_t alr[4];
                if (SPLIT==3){
                    uint4 l4 = *(const uint4*)(Al + kg*1024 + (wm*4+mt)*128 + lsw*4);
                    alr[0]=l4.x; alr[1]=l4.y; alr[2]=l4.z; alr[3]=l4.w;
                }
                #pragma unroll
                for (int nt=0;nt<4;nt++){
                    mma8(acc[mt][nt], ah, bhf[nt]);
                    if (SPLIT==3){
                        mma8(acc[mt][nt], ah, blf[nt]);
                        mma8(acc[mt][nt], alr, bhf[nt]);
                    }
                }
            }
        }
    };

    // prologue
    gload();
    store_tile(smem);
    __syncthreads();

    int nIter = K >> 4;
    for (int i = 0; i < nIter; i++) {
        uint32_t* cur = smem + (size_t)(i & 1) * NTW;
        uint32_t* nxt = smem + (size_t)((i & 1) ^ 1) * NTW;
        bool hasNext = (i + 1 < nIter);
        if (hasNext) gload();
        compute_tile(cur);
        if (hasNext) store_tile(nxt);
        __syncthreads();
    }

    // epilogue
    #pragma unroll
    for (int mt=0;mt<4;mt++){
        int r0 = brow + wm*64 + mt*16 + (lane>>2);
        #pragma unroll
        for (int nt=0;nt<4;nt++){
            int c = bcol + wn*32 + nt*8 + (lane&3)*2;
            float2 v0 = make_float2(acc[mt][nt][0], acc[mt][nt][1]);
            float2 v1 = make_float2(acc[mt][nt][2], acc[mt][nt][3]);
            if (bias){
                float b0=bias[c], b1=bias[c+1];
                v0.x+=b0; v0.y+=b1; v1.x+=b0; v1.y+=b1;
            }
            if (applyRelu){
                v0.x=fmaxf(v0.x,0.f); v0.y=fmaxf(v0.y,0.f);
                v1.x=fmaxf(v1.x,0.f); v1.y=fmaxf(v1.y,0.f);
            }
            if (res){
                v0.x += res[(long)r0*ldres + c];     v0.y += res[(long)r0*ldres + c+1];
                v1.x += res[(long)(r0+8)*ldres + c]; v1.y += res[(long)(r0+8)*ldres + c+1];
            }
            *(float2*)(Cm + (long)r0*ldc + c)     = v0;
            *(float2*)(Cm + (long)(r0+8)*ldc + c) = v1;
        }
    }
}

// ---------------- Flash attention with TF32 MMA (round-6 proven version) ----------------
// Q tile 64 rows/CTA; QK^T in 3xTF32 (score chain), PV in 1xTF32.
// K/V tiles for iteration kt+1 prefetched into registers during iteration kt.
#define QS 132
#define VSd 136
#define SSd 68
#define ATTN_WORDS (4*64*QS + 64*VSd + 64*SSd + 3*64 + 8*64)
#define ATTN_BYTES (ATTN_WORDS*4)

__global__ __launch_bounds__(256) void attn_mma(
    const float* __restrict__ Q, const float* __restrict__ K, const float* __restrict__ V,
    const float* __restrict__ x, float* __restrict__ x1)
{
    extern __shared__ uint32_t sm[];
    uint32_t* Qh = sm;
    uint32_t* Ql = Qh + 64*QS;
    uint32_t* Kh = Ql + 64*QS;
    uint32_t* Kl = Kh + 64*QS;
    uint32_t* Vt = Kl + 64*QS;
    float* Ssm  = (float*)(Vt + 64*VSd);
    float* mrow = Ssm + 64*SSd;
    float* lrow = mrow + 64;
    float* arow = lrow + 64;
    float* pmax = arow + 64;
    float* psum = pmax + 4*64;

    int bh = blockIdx.y; int b = bh>>3, h = bh&7;
    int q0 = blockIdx.x*64;
    int tid = threadIdx.x, lane = tid&31, wid = tid>>5;
    int wm = wid>>1, wn = wid&1;   // 4(m) x 2(n)

    const float* Qg = Q + ((long)b*Tn + q0)*Cn + h*Dn;
    const float* Kg = K + (long)b*Tn*Cn + h*Dn;
    const float* Vg = V + (long)b*Tn*Cn + h*Dn;

    // Load + split Q tile (once)
    #pragma unroll
    for (int it=0; it<8; it++){
        int idx = tid + it*256;
        int r = idx>>5, c = (idx&31)*4;
        float4 t = *(const float4*)(Qg + (long)r*Cn + c);
        float v[4] = {t.x,t.y,t.z,t.w};
        #pragma unroll
        for (int j=0;j<4;j++){
            uint32_t hh = cvt_tf32(v[j]);
            Qh[r*QS + c + j] = hh;
            Ql[r*QS + c + j] = cvt_tf32(v[j]-__uint_as_float(hh));
        }
    }
    if (tid < 64){ mrow[tid] = -1e30f; lrow[tid] = 0.f; }

    float accO[8][4];
    #pragma unroll
    for (int i=0;i<8;i++)
        #pragma unroll
        for (int j=0;j<4;j++) accO[i][j]=0.f;

    // register staging for K/V tiles
    float4 kreg[8], vreg[8];
    {
        #pragma unroll
        for (int it=0; it<8; it++){
            int idx = tid + it*256;
            int r = idx>>5, c = (idx&31)*4;
            kreg[it] = *(const float4*)(Kg + (long)r*Cn + c);
            vreg[it] = *(const float4*)(Vg + (long)r*Cn + c);
        }
    }

    for (int kt = 0; kt < Tn/64; kt++) {
        __syncthreads();   // prev PV / softmax reads done; Kt/Vs free
        // commit staged registers -> smem (convert + split)
        #pragma unroll
        for (int it=0; it<8; it++){
            int idx = tid + it*256;
            int r = idx>>5, c = (idx&31)*4;
            float v[4] = {kreg[it].x, kreg[it].y, kreg[it].z, kreg[it].w};
            #pragma unroll
            for (int j=0;j<4;j++){
                uint32_t hh = cvt_tf32(v[j]);
                Kh[r*QS + c + j] = hh;
                Kl[r*QS + c + j] = cvt_tf32(v[j]-__uint_as_float(hh));
            }
            uint4 uv;
            uv.x=cvt_tf32(vreg[it].x); uv.y=cvt_tf32(vreg[it].y);
            uv.z=cvt_tf32(vreg[it].z); uv.w=cvt_tf32(vreg[it].w);
            *(uint4*)(&Vt[r*VSd + c]) = uv;
        }
        __syncthreads();

        // prefetch next K/V tile into registers (latency hides behind compute)
        if (kt + 1 < Tn/64) {
            const float* Kgt = Kg + (long)(kt+1)*64*Cn;
            const float* Vgt = Vg + (long)(kt+1)*64*Cn;
            #pragma unroll
            for (int it=0; it<8; it++){
                int idx = tid + it*256;
                int r = idx>>5, c = (idx&31)*4;
                kreg[it] = *(const float4*)(Kgt + (long)r*Cn + c);
                vreg[it] = *(const float4*)(Vgt + (long)r*Cn + c);
            }
        }

        // S = Q K^T (3xTF32), warp tile 16x32
        float accS[4][4];
        #pragma unroll
        for (int i=0;i<4;i++)
            #pragma unroll
            for (int j=0;j<4;j++) accS[i][j]=0.f;

        #pragma unroll
        for (int ks=0; ks<128; ks+=8){
            int kk = ks + (lane&3);
            uint32_t bhf[4][2], blf[4][2];
            #pragma unroll
            for (int nt=0;nt<4;nt++){
                int c = wn*32 + nt*8 + (lane>>2);
                bhf[nt][0] = Kh[c*QS + kk];
                bhf[nt][1] = Kh[c*QS + kk + 4];
                blf[nt][0] = Kl[c*QS + kk];
                blf[nt][1] = Kl[c*QS + kk + 4];
            }
            int r = wm*16 + (lane>>2);
            uint32_t ah[4], al[4];
            ah[0]=Qh[r*QS+kk];     ah[1]=Qh[(r+8)*QS+kk];
            ah[2]=Qh[r*QS+kk+4];   ah[3]=Qh[(r+8)*QS+kk+4];
            al[0]=Ql[r*QS+kk];     al[1]=Ql[(r+8)*QS+kk];
            al[2]=Ql[r*QS+kk+4];   al[3]=Ql[(r+8)*QS+kk+4];
            #pragma unroll
            for (int nt=0;nt<4;nt++){
                mma8(accS[nt], ah, bhf[nt]);
                mma8(accS[nt], ah, blf[nt]);
                mma8(accS[nt], al, bhf[nt]);
            }
        }
        {
            int r = wm*16 + (lane>>2);
            #pragma unroll
            for (int nt=0;nt<4;nt++){
                int c = wn*32 + nt*8 + (lane&3)*2;
                Ssm[r*SSd + c]       = accS[nt][0]*SCALE;
                Ssm[r*SSd + c + 1]   = accS[nt][1]*SCALE;
                Ssm[(r+8)*SSd + c]   = accS[nt][2]*SCALE;
                Ssm[(r+8)*SSd + c+1] = accS[nt][3]*SCALE;
            }
        }
        __syncthreads();

        // softmax: 4 threads per row
        {
            int r = tid & 63, qd = tid >> 6;
            float* Sr = Ssm + r*SSd + qd*16;
            float mt_ = -1e30f;
            #pragma unroll
            for (int j=0;j<16;j++) mt_ = fmaxf(mt_, Sr[j]);
            pmax[qd*64 + r] = mt_;
            __syncthreads();
            float mold = mrow[r];
            float mnew = fmaxf(mold,
                         fmaxf(fmaxf(pmax[r], pmax[64+r]), fmaxf(pmax[128+r], pmax[192+r])));
            float s_ = 0.f;
            #pragma unroll
            for (int j=0;j<16;j++){
                float p = __expf(Sr[j] - mnew);
                Sr[j] = p; s_ += p;
            }
            psum[qd*64 + r] = s_;
            __syncthreads();
            if (qd == 0){
                float al_ = __expf(mold - mnew);
                lrow[r] = lrow[r]*al_ + psum[r] + psum[64+r] + psum[128+r] + psum[192+r];
                mrow[r] = mnew;
                arow[r] = al_;
            }
        }
        __syncthreads();

        // rescale + PV (1xTF32), warp tile 16x64
        {
            float a0 = arow[wm*16 + (lane>>2)];
            float a1 = arow[wm*16 + (lane>>2) + 8];
            #pragma unroll
            for (int nt=0;nt<8;nt++){
                accO[nt][0]*=a0; accO[nt][1]*=a0;
                accO[nt][2]*=a1; accO[nt][3]*=a1;
            }
            #pragma unroll
            for (int s0=0; s0<64; s0+=8){
                int kk = s0 + (lane&3);
                int r = wm*16 + (lane>>2);
                uint32_t ap[4];
                ap[0]=cvt_tf32(Ssm[r*SSd + kk]);
                ap[1]=cvt_tf32(Ssm[(r+8)*SSd + kk]);
                ap[2]=cvt_tf32(Ssm[r*SSd + kk + 4]);
                ap[3]=cvt_tf32(Ssm[(r+8)*SSd + kk + 4]);
                #pragma unroll
                for (int nt=0;nt<8;nt++){
                    int c = wn*64 + nt*8 + (lane>>2);
                    uint32_t bp[2] = { Vt[kk*VSd + c], Vt[(kk+4)*VSd + c] };
                    mma8(accO[nt], ap, bp);
                }
            }
        }
    }

    __syncthreads();
    // epilogue: x1 = x + O/l
    {
        int r = wm*16 + (lane>>2);
        float i0 = 1.f/lrow[r], i1 = 1.f/lrow[r+8];
        long row0 = (long)b*Tn + q0 + r;
        #pragma unroll
        for (int nt=0;nt<8;nt++){
            int c = h*Dn + wn*64 + nt*8 + (lane&3)*2;
            long o0 = row0*Cn + c, o1 = (row0+8)*Cn + c;
            float2 v0 = make_float2(accO[nt][0]*i0 + x[o0], accO[nt][1]*i0 + x[o0+1]);
            float2 v1 = make_float2(accO[nt][2]*i1 + x[o1], accO[nt][3]*i1 + x[o1+1]);
            *(float2*)(x1 + o0) = v0;
            *(float2*)(x1 + o1) = v1;
        }
    }
}

// ---------------- host launcher ----------------
extern "C" void kernel_launch(void* const* d_in, const int* in_sizes, int n_in,
                              void* d_out, int out_size)
{
    const float* x    = (const float*)d_in[0];
    const float* wq   = (const float*)d_in[1];
    const float* wk   = (const float*)d_in[2];
    const float* wv   = (const float*)d_in[3];
    const float* w1   = (const float*)d_in[4];
    const float* b1   = (const float*)d_in[5];
    const float* w2   = (const float*)d_in[6];
    const float* b2   = (const float*)d_in[7];
    const float* ln1g = (const float*)d_in[8];
    const float* ln1b = (const float*)d_in[9];
    const float* ln2g = (const float*)d_in[10];
    const float* ln2b = (const float*)d_in[11];
    float* out = (float*)d_out;

    float *h, *q, *k, *v, *x1, *h2, *ff;
    cudaGetSymbolAddress((void**)&h,  g_h);
    cudaGetSymbolAddress((void**)&q,  g_q);
    cudaGetSymbolAddress((void**)&k,  g_k);
    cudaGetSymbolAddress((void**)&v,  g_v);
    cudaGetSymbolAddress((void**)&x1, g_x1);
    cudaGetSymbolAddress((void**)&h2, g_h2);
    cudaGetSymbolAddress((void**)&ff, g_ff);

    // dynamic smem: split1 = 2*(2048+2112)*4 = 33280 B ; split3 = 66560 B
    const int SM1 = 2*(2048+2112)*4;
    const int SM3 = 2*(2*2048+2*2112)*4;

    cudaFuncSetAttribute(attn_mma, cudaFuncAttributeMaxDynamicSharedMemorySize,
                         ATTN_BYTES);
    cudaFuncSetAttribute(mma_gemm<1>, cudaFuncAttributeMaxDynamicSharedMemorySize, SM1);
    cudaFuncSetAttribute(mma_gemm<3>, cudaFuncAttributeMaxDynamicSharedMemorySize, SM3);

    // 1) LN1
    ln_kernel<<<Mrows, 256>>>(x, ln1g, ln1b, h);

    // 2) projections: q,k in 3xTF32 (score chain), v in 1xTF32
    dim3 pg(1, Mrows/128, Hn);
    mma_gemm<3><<<pg, 256, SM3>>>(h, wq, q, Mrows, Dn, Cn, Cn, Dn, Cn,
                             (long)Cn*Dn, (long)Dn, nullptr, 0, nullptr, 0);
    mma_gemm<3><<<pg, 256, SM3>>>(h, wk, k, Mrows, Dn, Cn, Cn, Dn, Cn,
                             (long)Cn*Dn, (long)Dn, nullptr, 0, nullptr, 0);
    mma_gemm<1><<<pg, 256, SM1>>>(h, wv, v, Mrows, Dn, Cn, Cn, Dn, Cn,
                             (long)Cn*Dn, (long)Dn, nullptr, 0, nullptr, 0);

    // 3) attention + residual
    attn_mma<<<dim3(Tn/64, Bsz*Hn), 256, ATTN_BYTES>>>(q, k, v, x, x1);

    // 4) LN2
    ln_kernel<<<Mrows, 256>>>(x1, ln2g, ln2b, h2);

    // 5) FF1: relu(h2 @ w1 + b1)
    mma_gemm<1><<<dim3(DffN/128, Mrows/128, 1), 256, SM1>>>(h2, w1, ff, Mrows, DffN, Cn,
                             Cn, DffN, DffN, 0L, 0L, b1, 1, nullptr, 0);

    // 6) FF2: out = x1 + (ff @ w2 + b2)
    mma_gemm<1><<<dim3(Cn/128, Mrows/128, 1), 256, SM1>>>(ff, w2, out, Mrows, Cn, DffN,
                             DffN, Cn, Cn, 0L, 0L, b2, 0, x1, Cn);
}